// round 11
// baseline (speedup 1.0000x reference)
#include <cuda_runtime.h>
#include <cstddef>

// LoG = GaussianBlur(3,sigma=1) -> Laplacian(ksize=9) + 1, clip [0,255].
// Fused: composite 11x11 = A(x)B(y) + B(x)A(y), A = P9*[1,2,1], B = P9*[1,-2,1],
// P9 = gauss3 (*) binom6. Horizontal pass computes hP (9-tap) once, derives
// U = [1,2,1]*hP, W = [1,-2,1]*hP; vertical: out = cB*U + cA*W (+1, clip).
// Banded: each block does a 256-row band in 8 iterations of 32 rows with a
// 64-slot (U,W) ring buffer -> the 10-row vertical halo is computed once.

#define Hn 512
#define Wn 512
#define ROWF 1536            // floats per image row (512*3)
#define TWP 32
#define BAND 256
#define NITER 8              // BAND / 32
#define IN_PITCH 44          // 16B-aligned rows (deinterleaved channel planes)
#define IN_PLANE 1848        // 42*44 (max rows per iteration)
#define HPP 66               // (U,W) float2 row pitch = 33
#define RING 64              // ring slots (power of two)
#define RING_PLANE (RING * HPP)   // 4224 floats per channel
#define NTHREADS 512

__device__ __forceinline__ int reflect101(int i, int n) {
    i = (i < 0) ? -i : i;
    return (i >= n) ? (2 * n - 2 - i) : i;
}

// ---- Phase 1: load NR input rows (abs rows abs0..abs0+NR-1) into in_s ------
template<int NR>
__device__ __forceinline__ void load_rows(const float* __restrict__ xp,
                                          float* in_s, int p0, int abs0, int tid) {
    if (p0 != 0 && p0 != (Wn - TWP)) {
        // interior-W fast path: float4 loads, no column reflect math
        const int fidx0 = (p0 - 5) * 3 - 1;          // 16B-aligned start
        const int col4  = tid & 31;
        int r = tid >> 5;                            // 0..15

        int qq[4], cc[4];
        bool val[4];
        #pragma unroll
        for (int l = 0; l < 4; l++) {
            int off = 4 * col4 + l - 1;
            val[l] = (off >= 0) && (off < 126);
            int o = val[l] ? off : 0;
            qq[l] = o / 3;
            cc[l] = o - 3 * qq[l];
        }
        const float4* gp = (const float4*)(xp + fidx0 + 4 * col4);

        #pragma unroll
        for (int k = 0; k < (NR + 15) / 16; k++) {
            if (r < NR) {
                const int gh = reflect101(abs0 + r, Hn);
                float4 v = gp[gh * (ROWF / 4)];
                float vv[4] = {v.x, v.y, v.z, v.w};
                const int rb = r * IN_PITCH;
                #pragma unroll
                for (int l = 0; l < 4; l++)
                    if (val[l]) in_s[cc[l] * IN_PLANE + rb + qq[l]] = vv[l];
            }
            r += 16;
        }
    } else {
        // border-W scalar path (reflect both dims)
        const int f  = tid & 127;
        const int rg = tid >> 7;                     // 0..3
        if (f < 126) {
            const int q = f / 3;
            const int c = f - q * 3;
            const int wp = reflect101(p0 - 5 + q, Wn);
            const int src_col = wp * 3 + c;
            float* dst = in_s + c * IN_PLANE + q;
            for (int r = rg; r < NR; r += 4) {
                const int gh = reflect101(abs0 + r, Hn);
                dst[r * IN_PITCH] = xp[(size_t)gh * ROWF + src_col];
            }
        }
    }
}

// ---- Phase 2: horizontal 9-tap hP -> (U,W) into ring slots -----------------
template<int NR>
__device__ __forceinline__ void hconv_rows(const float* in_s, float* hAB_s,
                                           int abs0, int tid) {
    const float P9[9] = {
        0.2740686191f,  2.0962744762f,  7.0962744762f, 13.9037255238f,
        17.2593138094f, 13.9037255238f, 7.0962744762f,  2.0962744762f,
        0.2740686191f };

    if (tid < 3 * NR * 4) {
        const int c   = tid / (NR * 4);
        const int rem = tid - c * (NR * 4);
        const int r   = rem >> 2;
        const int p   = (rem & 3) << 3;
        const float* src = in_s + c * IN_PLANE + r * IN_PITCH + p;

        float hP[10];
        #pragma unroll
        for (int m = 0; m < 10; m++) hP[m] = 0.f;

        #pragma unroll
        for (int ib = 0; ib < 4; ib++) {
            float4 v4 = *(const float4*)(src + 4 * ib);
            float vs[4] = {v4.x, v4.y, v4.z, v4.w};
            #pragma unroll
            for (int s = 0; s < 4; s++) {
                const int i = 4 * ib + s;
                const float v = vs[s];
                #pragma unroll
                for (int m = 0; m < 10; m++) {
                    const int t = i - m;
                    if (t >= 0 && t < 9)
                        hP[m] = fmaf(P9[t], v, hP[m]);
                }
            }
        }
        {
            float2 v2 = *(const float2*)(src + 16);
            float vs[2] = {v2.x, v2.y};
            #pragma unroll
            for (int s = 0; s < 2; s++) {
                const int i = 16 + s;
                const float v = vs[s];
                #pragma unroll
                for (int m = 0; m < 10; m++) {
                    const int t = i - m;
                    if (t >= 0 && t < 9)
                        hP[m] = fmaf(P9[t], v, hP[m]);
                }
            }
        }

        const int slot = (abs0 + r + RING) & (RING - 1);
        float2* d = (float2*)(hAB_s + c * RING_PLANE + slot * HPP) + p;
        #pragma unroll
        for (int j = 0; j < 8; j++) {
            const float s2 = hP[j] + hP[j + 2];
            d[j] = make_float2(fmaf(2.0f, hP[j + 1], s2),
                               fmaf(-2.0f, hP[j + 1], s2));
        }
    }
}

// ---- Phase 3: vertical 11-tap combine from ring, 16-row chunks -------------
__device__ __forceinline__ void vconv_out(const float* hAB_s, float* __restrict__ out,
                                          size_t plane, int p0, int orow0, int tid) {
    const float cA[11] = {
        0.274068619061f,  2.644411714f, 11.562892048f, 30.192548953f,
        52.163039333f,   62.326078667f, 52.163039333f, 30.192548953f,
        11.562892048f,    2.644411714f,  0.274068619061f };
    const float cB[11] = {
        0.274068619061f,  1.548137238f,  3.177794143f,  1.807451048f,
       -3.451862762f,    -6.711176571f, -3.451862762f,  1.807451048f,
        3.177794143f,     1.548137238f,  0.274068619061f };

    if (tid < 192) {
        const int col   = tid % 96;      // consecutive tid -> consecutive floats
        const int chunk = tid / 96;
        const int p = col / 3;
        const int c = col - p * 3;
        const int r0 = chunk * 16;
        const int s0 = (orow0 + r0 - 5 + RING) & (RING - 1);
        const float2* bp = (const float2*)(hAB_s + c * RING_PLANE) + p;

        float acc[16];
        #pragma unroll
        for (int j = 0; j < 16; j++) acc[j] = 1.0f;   // delta = 1

        #pragma unroll
        for (int i = 0; i < 26; i++) {
            const int si = (s0 + i) & (RING - 1);
            const float2 v = bp[si * (HPP / 2)];      // (U, W)
            #pragma unroll
            for (int j = 0; j < 16; j++) {
                const int t = i - j;
                if (t >= 0 && t < 11) {
                    acc[j] = fmaf(cB[t], v.x, acc[j]);
                    acc[j] = fmaf(cA[t], v.y, acc[j]);
                }
            }
        }
        float* op = out + plane + (size_t)(orow0 + r0) * ROWF + p0 * 3 + col;
        #pragma unroll
        for (int j = 0; j < 16; j++)
            op[j * ROWF] = fminf(fmaxf(acc[j], 0.0f), 255.0f);
    }
}

__global__ __launch_bounds__(NTHREADS, 3)
void log_fused_kernel(const float* __restrict__ x, float* __restrict__ out) {
    extern __shared__ float smem[];
    float* in_s  = smem;                      // 3 planes [42][IN_PITCH]
    float* hAB_s = smem + 3 * IN_PLANE;       // 3 planes [RING][HPP] (U,W) ring

    const int tid   = threadIdx.x;
    const int p0    = blockIdx.x * TWP;
    const int band0 = blockIdx.y * BAND;
    const size_t plane = (size_t)blockIdx.z * (size_t)(Hn * ROWF);
    const float* xp = x + plane;

    // --- iteration 0: full 42-row window ---
    load_rows<42>(xp, in_s, p0, band0 - 5, tid);
    __syncthreads();
    hconv_rows<42>(in_s, hAB_s, band0 - 5, tid);
    __syncthreads();
    vconv_out(hAB_s, out, plane, p0, band0, tid);

    // --- iterations 1..7: 32 new rows each, halo reused from ring ---
    #pragma unroll 1
    for (int it = 1; it < NITER; it++) {
        const int new0 = band0 + 32 * it + 5;   // first new UW/input row
        __syncthreads();
        load_rows<32>(xp, in_s, p0, new0, tid);
        __syncthreads();
        hconv_rows<32>(in_s, hAB_s, new0, tid);
        __syncthreads();
        vconv_out(hAB_s, out, plane, p0, band0 + 32 * it, tid);
    }
}

extern "C" void kernel_launch(void* const* d_in, const int* in_sizes, int n_in,
                              void* d_out, int out_size) {
    const float* x = (const float*)d_in[0];
    float* out = (float*)d_out;
    const int N = in_sizes[0] / (Hn * Wn * 3);

    const int smem_bytes = (3 * IN_PLANE + 3 * RING_PLANE) * (int)sizeof(float);
    cudaFuncSetAttribute(log_fused_kernel,
                         cudaFuncAttributeMaxDynamicSharedMemorySize, smem_bytes);

    dim3 grid(Wn / TWP, Hn / BAND, N);   // (16, 2, N)
    log_fused_kernel<<<grid, NTHREADS, smem_bytes>>>(x, out);
}

// round 12
// speedup vs baseline: 1.1607x; 1.1607x over previous
#include <cuda_runtime.h>
#include <cstddef>

// LoG = GaussianBlur(3,sigma=1) -> Laplacian(ksize=9) + 1, clip [0,255].
// Fused: composite 11x11 = A(x)B(y) + B(x)A(y), A = P9*[1,2,1], B = P9*[1,-2,1],
// P9 = gauss3 (*) binom6. Horizontal pass computes hP (9-tap) once, derives
// U = [1,2,1]*hP, W = [1,-2,1]*hP; vertical: out = cB*U + cA*W (+1, clip).
// Banded: 64-row band in 2 iterations of 32 rows with a 42-slot (U,W) ring
// (same smem footprint as the 32-row tile) -> vertical halo computed once.

#define Hn 512
#define Wn 512
#define ROWF 1536            // floats per image row (512*3)
#define TWP 32
#define BAND 64
#define IN_PITCH 44          // 16B-aligned rows (deinterleaved channel planes)
#define IN_PLANE 1848        // 42*44
#define HPP 66               // (U,W) float2 row pitch = 33
#define RNG 42               // ring slots (= live row window)
#define HAB_PLANE 2774       // 42*66=2772 +2; /2 = 1387 == 11 mod 16
#define NTHREADS 512

__device__ __forceinline__ int reflect101(int i, int n) {
    i = (i < 0) ? -i : i;
    return (i >= n) ? (2 * n - 2 - i) : i;
}
__device__ __forceinline__ int mod42(int x) { return x % 42; }   // x >= 0

// ---- Phase 1: load NR rows (abs rows abs0..abs0+NR-1) into in_s rows 0.. ---
template<int NR>
__device__ __forceinline__ void load_rows(const float* __restrict__ xp,
                                          float* in_s, int p0, int abs0, int tid) {
    if (p0 != 0 && p0 != (Wn - TWP)) {
        const int fidx0 = (p0 - 5) * 3 - 1;          // 16B-aligned start
        const int col4  = tid & 31;
        int r = tid >> 5;                            // 0..15
        int qq[4], cc[4];
        bool val[4];
        #pragma unroll
        for (int l = 0; l < 4; l++) {
            int off = 4 * col4 + l - 1;
            val[l] = (off >= 0) && (off < 126);
            int o = val[l] ? off : 0;
            qq[l] = o / 3;
            cc[l] = o - 3 * qq[l];
        }
        const float4* gp = (const float4*)(xp + fidx0 + 4 * col4);
        #pragma unroll
        for (int k = 0; k < (NR + 15) / 16; k++) {
            if (r < NR) {
                const int gh = reflect101(abs0 + r, Hn);
                float4 v = gp[gh * (ROWF / 4)];
                float vv[4] = {v.x, v.y, v.z, v.w};
                const int rb = r * IN_PITCH;
                #pragma unroll
                for (int l = 0; l < 4; l++)
                    if (val[l]) in_s[cc[l] * IN_PLANE + rb + qq[l]] = vv[l];
            }
            r += 16;
        }
    } else {
        const int f  = tid & 127;
        const int rg = tid >> 7;                     // 0..3
        if (f < 126) {
            const int q = f / 3;
            const int c = f - q * 3;
            const int wp = reflect101(p0 - 5 + q, Wn);
            const int src_col = wp * 3 + c;
            float* dst = in_s + c * IN_PLANE + q;
            #pragma unroll 4
            for (int r = rg; r < NR; r += 4) {
                const int gh = reflect101(abs0 + r, Hn);
                dst[r * IN_PITCH] = xp[(size_t)gh * ROWF + src_col];
            }
        }
    }
}

// ---- Phase 2: horizontal 9-tap hP -> (U,W) into ring slot (abs row mod 42) -
template<int NR>
__device__ __forceinline__ void hconv_rows(const float* in_s, float* hAB_s,
                                           int abs0, int tid) {
    const float P9[9] = {
        0.2740686191f,  2.0962744762f,  7.0962744762f, 13.9037255238f,
        17.2593138094f, 13.9037255238f, 7.0962744762f,  2.0962744762f,
        0.2740686191f };

    if (tid < 3 * NR * 4) {
        int c, rem;
        if (NR == 32) { c = tid >> 7; rem = tid & 127; }
        else          { c = tid / (NR * 4); rem = tid - c * (NR * 4); }
        const int r = rem >> 2;
        const int p = (rem & 3) << 3;
        const float* src = in_s + c * IN_PLANE + r * IN_PITCH + p;

        float hP[10];
        #pragma unroll
        for (int m = 0; m < 10; m++) hP[m] = 0.f;

        #pragma unroll
        for (int ib = 0; ib < 4; ib++) {
            float4 v4 = *(const float4*)(src + 4 * ib);
            float vs[4] = {v4.x, v4.y, v4.z, v4.w};
            #pragma unroll
            for (int s = 0; s < 4; s++) {
                const int i = 4 * ib + s;
                const float v = vs[s];
                #pragma unroll
                for (int m = 0; m < 10; m++) {
                    const int t = i - m;
                    if (t >= 0 && t < 9) hP[m] = fmaf(P9[t], v, hP[m]);
                }
            }
        }
        {
            float2 v2 = *(const float2*)(src + 16);
            float vs[2] = {v2.x, v2.y};
            #pragma unroll
            for (int s = 0; s < 2; s++) {
                const int i = 16 + s;
                const float v = vs[s];
                #pragma unroll
                for (int m = 0; m < 10; m++) {
                    const int t = i - m;
                    if (t >= 0 && t < 9) hP[m] = fmaf(P9[t], v, hP[m]);
                }
            }
        }

        const int slot = mod42(abs0 + r + 84);       // abs0 >= -5
        float2* d = (float2*)(hAB_s + c * HAB_PLANE + slot * HPP) + p;
        #pragma unroll
        for (int j = 0; j < 8; j++) {
            const float s2 = hP[j] + hP[j + 2];
            d[j] = make_float2(fmaf(2.0f, hP[j + 1], s2),
                               fmaf(-2.0f, hP[j + 1], s2));
        }
    }
}

// ---- Phase 3: vertical 11-tap combine from ring, 16-row chunks -------------
__device__ __forceinline__ void vconv_out(const float* hAB_s, float* __restrict__ out,
                                          size_t plane, int p0, int orow0, int tid) {
    const float cA[11] = {
        0.274068619061f,  2.644411714f, 11.562892048f, 30.192548953f,
        52.163039333f,   62.326078667f, 52.163039333f, 30.192548953f,
        11.562892048f,    2.644411714f,  0.274068619061f };
    const float cB[11] = {
        0.274068619061f,  1.548137238f,  3.177794143f,  1.807451048f,
       -3.451862762f,    -6.711176571f, -3.451862762f,  1.807451048f,
        3.177794143f,     1.548137238f,  0.274068619061f };

    if (tid < 192) {
        const int col   = tid % 96;      // consecutive tid -> consecutive floats
        const int chunk = tid / 96;
        const int p = col / 3;
        const int c = col - p * 3;
        const int r0 = chunk * 16;
        const float2* bp = (const float2*)(hAB_s + c * HAB_PLANE) + p;

        int si = mod42(orow0 + r0 + 79);             // (orow0 + r0 - 5) mod 42
        float acc[16];
        #pragma unroll
        for (int j = 0; j < 16; j++) acc[j] = 1.0f;  // delta = 1

        #pragma unroll
        for (int i = 0; i < 26; i++) {
            const float2 v = bp[si * (HPP / 2)];     // (U, W)
            si++;
            if (si == RNG) si = 0;
            #pragma unroll
            for (int j = 0; j < 16; j++) {
                const int t = i - j;
                if (t >= 0 && t < 11) {
                    acc[j] = fmaf(cB[t], v.x, acc[j]);
                    acc[j] = fmaf(cA[t], v.y, acc[j]);
                }
            }
        }
        float* op = out + plane + (size_t)orow0 * ROWF + (size_t)r0 * ROWF + p0 * 3 + col;
        #pragma unroll
        for (int j = 0; j < 16; j++)
            op[j * ROWF] = fminf(fmaxf(acc[j], 0.0f), 255.0f);
    }
}

__global__ __launch_bounds__(NTHREADS, 4)
void log_fused_kernel(const float* __restrict__ x, float* __restrict__ out) {
    extern __shared__ float smem[];
    float* in_s  = smem;                      // 3 planes [42][IN_PITCH]
    float* hAB_s = smem + 3 * IN_PLANE;       // 3 planes [RNG][HPP] (U,W) ring

    const int tid   = threadIdx.x;
    const int p0    = blockIdx.x * TWP;
    const int band0 = blockIdx.y * BAND;
    const size_t plane = (size_t)blockIdx.z * (size_t)(Hn * ROWF);
    const float* xp = x + plane;

    // --- iteration 0: full 42-row window, outputs band0..band0+31 ---
    load_rows<42>(xp, in_s, p0, band0 - 5, tid);
    __syncthreads();
    hconv_rows<42>(in_s, hAB_s, band0 - 5, tid);
    __syncthreads();
    vconv_out(hAB_s, out, plane, p0, band0, tid);

    // --- iteration 1: 32 new rows, halo reused; outputs band0+32..+63 ---
    // load may overlap other warps' vconv (disjoint buffers); the sync after
    // load orders vconv's ring reads before hconv's ring writes.
    load_rows<32>(xp, in_s, p0, band0 + 37, tid);
    __syncthreads();
    hconv_rows<32>(in_s, hAB_s, band0 + 37, tid);
    __syncthreads();
    vconv_out(hAB_s, out, plane, p0, band0 + 32, tid);
}

extern "C" void kernel_launch(void* const* d_in, const int* in_sizes, int n_in,
                              void* d_out, int out_size) {
    const float* x = (const float*)d_in[0];
    float* out = (float*)d_out;
    const int N = in_sizes[0] / (Hn * Wn * 3);

    const int smem_bytes = (3 * IN_PLANE + 3 * HAB_PLANE) * (int)sizeof(float);
    cudaFuncSetAttribute(log_fused_kernel,
                         cudaFuncAttributeMaxDynamicSharedMemorySize, smem_bytes);

    dim3 grid(Wn / TWP, Hn / BAND, N);   // (16, 8, N)
    log_fused_kernel<<<grid, NTHREADS, smem_bytes>>>(x, out);
}

// round 13
// speedup vs baseline: 1.1999x; 1.0338x over previous
#include <cuda_runtime.h>
#include <cstddef>

// LoG = GaussianBlur(3,sigma=1) -> Laplacian(ksize=9) + 1, clip [0,255].
// Fused: composite 11x11 = A(x)B(y) + B(x)A(y), A = P9*[1,2,1], B = P9*[1,-2,1],
// P9 = gauss3 (*) binom6. Horizontal pass computes hP (9-tap) once, derives
// U = [1,2,1]*hP, W = [1,-2,1]*hP; vertical: out = cB*U + cA*W (+1, clip).
// Banded: 64-row band in 2 iterations of 32 rows; 42-slot (U,W) ring with
// slot(row) = (row - band0 + 5) mod 42, which makes every slot computation a
// compile-time identity (iter0/iter1 h-conv: slot == local r; iter0 v-conv:
// no wrap; iter1 v-conv: single conditional subtract).

#define Hn 512
#define Wn 512
#define ROWF 1536            // floats per image row (512*3)
#define TWP 32
#define BAND 64
#define IN_PITCH 44          // 16B-aligned rows (deinterleaved channel planes)
#define IN_PLANE 1848        // 42*44
#define HPP 66               // (U,W) float2 row pitch = 33
#define RNG 42               // ring slots (= live row window)
#define HAB_PLANE 2774       // 42*66=2772 +2; /2 = 1387 == 11 mod 16
#define NTHREADS 512

__device__ __forceinline__ int reflect101(int i, int n) {
    i = (i < 0) ? -i : i;
    return (i >= n) ? (2 * n - 2 - i) : i;
}

// ---- Phase 1: load NR rows (abs rows abs0..abs0+NR-1) into in_s rows 0.. ---
template<int NR>
__device__ __forceinline__ void load_rows(const float* __restrict__ xp,
                                          float* in_s, int p0, int abs0, int tid) {
    if (p0 != 0 && p0 != (Wn - TWP)) {
        const int fidx0 = (p0 - 5) * 3 - 1;          // 16B-aligned start
        const int col4  = tid & 31;
        int r = tid >> 5;                            // 0..15
        int qq[4], cc[4];
        bool val[4];
        #pragma unroll
        for (int l = 0; l < 4; l++) {
            int off = 4 * col4 + l - 1;
            val[l] = (off >= 0) && (off < 126);
            int o = val[l] ? off : 0;
            qq[l] = o / 3;
            cc[l] = o - 3 * qq[l];
        }
        const float4* gp = (const float4*)(xp + fidx0 + 4 * col4);
        #pragma unroll
        for (int k = 0; k < (NR + 15) / 16; k++) {
            if (r < NR) {
                const int gh = reflect101(abs0 + r, Hn);
                float4 v = gp[gh * (ROWF / 4)];
                float vv[4] = {v.x, v.y, v.z, v.w};
                const int rb = r * IN_PITCH;
                #pragma unroll
                for (int l = 0; l < 4; l++)
                    if (val[l]) in_s[cc[l] * IN_PLANE + rb + qq[l]] = vv[l];
            }
            r += 16;
        }
    } else {
        const int f  = tid & 127;
        const int rg = tid >> 7;                     // 0..3
        if (f < 126) {
            const int q = f / 3;
            const int c = f - q * 3;
            const int wp = reflect101(p0 - 5 + q, Wn);
            const int src_col = wp * 3 + c;
            float* dst = in_s + c * IN_PLANE + q;
            #pragma unroll 4
            for (int r = rg; r < NR; r += 4) {
                const int gh = reflect101(abs0 + r, Hn);
                dst[r * IN_PITCH] = xp[(size_t)gh * ROWF + src_col];
            }
        }
    }
}

// ---- Phase 2: horizontal 9-tap hP -> (U,W); ring slot == local row r --------
template<int NR>
__device__ __forceinline__ void hconv_rows(const float* in_s, float* hAB_s, int tid) {
    const float P9[9] = {
        0.2740686191f,  2.0962744762f,  7.0962744762f, 13.9037255238f,
        17.2593138094f, 13.9037255238f, 7.0962744762f,  2.0962744762f,
        0.2740686191f };

    if (tid < 3 * NR * 4) {
        int c, rem;
        if (NR == 32) { c = tid >> 7; rem = tid & 127; }
        else          { c = tid / (NR * 4); rem = tid - c * (NR * 4); }
        const int r = rem >> 2;
        const int p = (rem & 3) << 3;
        const float* src = in_s + c * IN_PLANE + r * IN_PITCH + p;

        float hP[10];
        #pragma unroll
        for (int m = 0; m < 10; m++) hP[m] = 0.f;

        #pragma unroll
        for (int ib = 0; ib < 4; ib++) {
            float4 v4 = *(const float4*)(src + 4 * ib);
            float vs[4] = {v4.x, v4.y, v4.z, v4.w};
            #pragma unroll
            for (int s = 0; s < 4; s++) {
                const int i = 4 * ib + s;
                const float v = vs[s];
                #pragma unroll
                for (int m = 0; m < 10; m++) {
                    const int t = i - m;
                    if (t >= 0 && t < 9) hP[m] = fmaf(P9[t], v, hP[m]);
                }
            }
        }
        {
            float2 v2 = *(const float2*)(src + 16);
            float vs[2] = {v2.x, v2.y};
            #pragma unroll
            for (int s = 0; s < 2; s++) {
                const int i = 16 + s;
                const float v = vs[s];
                #pragma unroll
                for (int m = 0; m < 10; m++) {
                    const int t = i - m;
                    if (t >= 0 && t < 9) hP[m] = fmaf(P9[t], v, hP[m]);
                }
            }
        }

        // slot(row) = (row - band0 + 5) mod 42 == r for both iterations:
        //   iter0: rows band0-5+r  -> r
        //   iter1: rows band0+37+r -> (42 + r) mod 42 = r
        float2* d = (float2*)(hAB_s + c * HAB_PLANE + r * HPP) + p;
        #pragma unroll
        for (int j = 0; j < 8; j++) {
            const float s2 = hP[j] + hP[j + 2];
            d[j] = make_float2(fmaf(2.0f, hP[j + 1], s2),
                               fmaf(-2.0f, hP[j + 1], s2));
        }
    }
}

// ---- Phase 3: vertical 11-tap combine from ring, 16-row chunks --------------
// OFF = output-row offset within the band (0 or 32). Ring slot for tap i of
// chunk r0 is (OFF + r0 + i) mod 42: OFF=0 never wraps; OFF=32 wraps at most once.
template<int OFF>
__device__ __forceinline__ void vconv_out(const float* hAB_s, float* __restrict__ out,
                                          size_t plane, int p0, int band0, int tid) {
    const float cA[11] = {
        0.274068619061f,  2.644411714f, 11.562892048f, 30.192548953f,
        52.163039333f,   62.326078667f, 52.163039333f, 30.192548953f,
        11.562892048f,    2.644411714f,  0.274068619061f };
    const float cB[11] = {
        0.274068619061f,  1.548137238f,  3.177794143f,  1.807451048f,
       -3.451862762f,    -6.711176571f, -3.451862762f,  1.807451048f,
        3.177794143f,     1.548137238f,  0.274068619061f };

    if (tid < 192) {
        const int col   = tid % 96;      // consecutive tid -> consecutive floats
        const int chunk = tid / 96;
        const int p = col / 3;
        const int c = col - p * 3;
        const int r0 = chunk * 16;
        const float2* bp = (const float2*)(hAB_s + c * HAB_PLANE) + p;

        float acc[16];
        #pragma unroll
        for (int j = 0; j < 16; j++) acc[j] = 1.0f;  // delta = 1

        if (OFF == 0) {
            // slots r0..r0+25, max 41: no wrap, plain indexing
            #pragma unroll
            for (int i = 0; i < 26; i++) {
                const float2 v = bp[(r0 + i) * (HPP / 2)];
                #pragma unroll
                for (int j = 0; j < 16; j++) {
                    const int t = i - j;
                    if (t >= 0 && t < 11) {
                        acc[j] = fmaf(cB[t], v.x, acc[j]);
                        acc[j] = fmaf(cA[t], v.y, acc[j]);
                    }
                }
            }
        } else {
            int si = OFF + r0;
            if (si >= RNG) si -= RNG;
            #pragma unroll
            for (int i = 0; i < 26; i++) {
                const float2 v = bp[si * (HPP / 2)];
                si++;
                if (si == RNG) si = 0;
                #pragma unroll
                for (int j = 0; j < 16; j++) {
                    const int t = i - j;
                    if (t >= 0 && t < 11) {
                        acc[j] = fmaf(cB[t], v.x, acc[j]);
                        acc[j] = fmaf(cA[t], v.y, acc[j]);
                    }
                }
            }
        }
        float* op = out + plane + (size_t)(band0 + OFF + r0) * ROWF + p0 * 3 + col;
        #pragma unroll
        for (int j = 0; j < 16; j++)
            op[j * ROWF] = fminf(fmaxf(acc[j], 0.0f), 255.0f);
    }
}

__global__ __launch_bounds__(NTHREADS, 4)
void log_fused_kernel(const float* __restrict__ x, float* __restrict__ out) {
    extern __shared__ float smem[];
    float* in_s  = smem;                      // 3 planes [42][IN_PITCH]
    float* hAB_s = smem + 3 * IN_PLANE;       // 3 planes [RNG][HPP] (U,W) ring

    const int tid   = threadIdx.x;
    const int p0    = blockIdx.x * TWP;
    const int band0 = blockIdx.y * BAND;
    const size_t plane = (size_t)blockIdx.z * (size_t)(Hn * ROWF);
    const float* xp = x + plane;

    // --- iteration 0: full 42-row window, outputs band0..band0+31 ---
    load_rows<42>(xp, in_s, p0, band0 - 5, tid);
    __syncthreads();
    hconv_rows<42>(in_s, hAB_s, tid);
    __syncthreads();
    vconv_out<0>(hAB_s, out, plane, p0, band0, tid);

    // --- iteration 1: 32 new rows (slots 0..31), outputs band0+32..+63 ---
    // load overlaps other warps' vconv (disjoint buffers); the sync after load
    // orders vconv's ring reads before hconv's ring writes.
    load_rows<32>(xp, in_s, p0, band0 + 37, tid);
    __syncthreads();
    hconv_rows<32>(in_s, hAB_s, tid);
    __syncthreads();
    vconv_out<32>(hAB_s, out, plane, p0, band0, tid);
}

extern "C" void kernel_launch(void* const* d_in, const int* in_sizes, int n_in,
                              void* d_out, int out_size) {
    const float* x = (const float*)d_in[0];
    float* out = (float*)d_out;
    const int N = in_sizes[0] / (Hn * Wn * 3);

    const int smem_bytes = (3 * IN_PLANE + 3 * HAB_PLANE) * (int)sizeof(float);
    cudaFuncSetAttribute(log_fused_kernel,
                         cudaFuncAttributeMaxDynamicSharedMemorySize, smem_bytes);

    dim3 grid(Wn / TWP, Hn / BAND, N);   // (16, 8, N)
    log_fused_kernel<<<grid, NTHREADS, smem_bytes>>>(x, out);
}